// round 12
// baseline (speedup 1.0000x reference)
#include <cuda_runtime.h>
#include <cuda_fp16.h>
#include <math.h>
#include <stdint.h>

#define Bn 16
#define Cc 512
#define Hh 50
#define Ww 50
#define Aa 9
#define Nn (Hh*Ww*Aa)   // 22500
#define Mm 16
#define LOSS_BLOCKS ((Bn*Nn + 255)/256)  // 1407

#define PADW 52
#define PROWS 2816
#define Kk 4608
#define PTILES 21
#define NTILES 4

// conv smem (K=128 per iteration):
//   A per-(ci2,kh) tile 132 rows x 128 ci fp16, stride 272B, 2 stages;
//   B tile 128 co x 128 k fp16, stride 272B, 3 stages.
#define ASTRIDE 272
#define A2_ROWS 132
#define A2_MAT 35968                  // 132*272 = 35904, pad to 128
#define B2_MAT 34816                  // 128*272
#define DYN_SMEM (2*A2_MAT + 3*B2_MAT)  // 176384 -> 1 CTA/SM

// head GEMM: M=40192, N=48, K=512, fp16 single pass
#define HROWS 40192
#define H_AST 18432                   // 128*144 per stage
#define H_WSTRIDE 1040
#define H_WBYTES (48*H_WSTRIDE)       // 49920
#define H_SMEM (3*H_AST + H_WBYTES)   // 105216
#define H_CHUNKS 8

// -------- scratch --------
__device__ float g_logits[Bn*Nn];
__device__ float g_pred[Bn*Nn*4];
__device__ float g_maxiou[Bn*Mm];
__device__ float g_part[LOSS_BLOCKS*5];
__device__ float4 g_anchor[Nn];
__device__ __align__(16) __half g_af[(size_t)Bn*PROWS*Cc];
__device__ __align__(16) __half g_bf[(size_t)Cc*Kk];
__device__ __align__(16) __half g_xf[(size_t)HROWS*Cc];
__device__ __align__(16) __half g_wf[48*Cc];

// ============ PTX helpers ============
#define CP_ASYNC16(dst, src) \
    asm volatile("cp.async.cg.shared.global [%0], [%1], 16;" :: "r"(dst), "l"(src))
#define CP_COMMIT() asm volatile("cp.async.commit_group;" ::: "memory")
#define CP_WAIT2()  asm volatile("cp.async.wait_group 2;" ::: "memory")
#define CP_WAIT1()  asm volatile("cp.async.wait_group 1;" ::: "memory")
#define CP_WAIT0()  asm volatile("cp.async.wait_group 0;" ::: "memory")

#define LDSM_X4(r0, r1, r2, r3, addr) \
    asm volatile("ldmatrix.sync.aligned.m8n8.x4.shared.b16 {%0,%1,%2,%3}, [%4];" \
        : "=r"(r0), "=r"(r1), "=r"(r2), "=r"(r3) : "r"(addr))
#define LDSM_X2(r0, r1, addr) \
    asm volatile("ldmatrix.sync.aligned.m8n8.x2.shared.b16 {%0,%1}, [%2];" \
        : "=r"(r0), "=r"(r1) : "r"(addr))

#define MMAF16(d, a, b) \
    asm volatile("mma.sync.aligned.m16n8k16.row.col.f32.f16.f16.f32 " \
        "{%0,%1,%2,%3}, {%4,%5,%6,%7}, {%8,%9}, {%0,%1,%2,%3};" \
        : "+f"((d)[0]), "+f"((d)[1]), "+f"((d)[2]), "+f"((d)[3]) \
        : "r"((a)[0]), "r"((a)[1]), "r"((a)[2]), "r"((a)[3]), "r"((b)[0]), "r"((b)[1]))

// ============ shared math helpers ============
__device__ __forceinline__ void anchor_geom(int n, float* ax1, float* ay1, float* ax2, float* ay2) {
    int a  = n % Aa;
    int i1 = (n / Aa) % Hh;
    int i0 = n / (Aa * Hh);
    const float SC[3] = {2.f, 4.f, 6.f};
    const float RA[3] = {0.5f, 1.f, 1.5f};
    float ws = SC[a % 3] * RA[a / 3];
    float hs = SC[a % 3];
    float cx = (float)i0 + 0.5f;
    float cy = (float)i1 + 0.5f;
    *ax1 = fminf(fmaxf(cx - ws * 0.5f, 0.f), 50.f);
    *ax2 = fminf(fmaxf(cx + ws * 0.5f, 0.f), 50.f);
    *ay1 = fminf(fmaxf(cy - hs * 0.5f, 0.f), 50.f);
    *ay2 = fminf(fmaxf(cy + hs * 0.5f, 0.f), 50.f);
}
// noinline: maxiou and loss must produce bitwise-identical iou values
__device__ __noinline__ float iou_fn(float ax1, float ay1, float ax2, float ay2,
                                     float gx1, float gy1, float gx2, float gy2) {
    float ix1 = fmaxf(ax1, gx1);
    float iy1 = fmaxf(ay1, gy1);
    float ix2 = fminf(ax2, gx2);
    float iy2 = fminf(ay2, gy2);
    float iw = fmaxf(ix2 - ix1, 0.f);
    float ih = fmaxf(iy2 - iy1, 0.f);
    float inter = iw * ih;
    float aa = (ax2 - ax1) * (ay2 - ay1);
    float ag = (gx2 - gx1) * (gy2 - gy1);
    return inter / (aa + ag - inter + 1e-8f);
}
__device__ __forceinline__ float softplus_f(float x) {
    return fmaxf(x, 0.f) + log1pf(expf(-fabsf(x)));
}
__device__ __forceinline__ float sl1(float d) {
    float a = fabsf(d);
    return (a < 1.f) ? 0.5f * d * d : a - 0.5f;
}

// ============ 0) zero the padding positions of the A slab ============
__global__ __launch_bounds__(256) void zero_pad_kernel() {
    int idx = blockIdx.x * 256 + threadIdx.x;
    const int PER = 64;
    int pos_id = idx / PER;
    int which = idx % PER;
    if (pos_id >= Bn * 316) return;
    int b = pos_id / 316;
    int j = pos_id % 316;
    int p;
    if (j < 52) p = j;
    else if (j < 152) { int r = 1 + (j - 52) / 2; p = r * PADW + (((j - 52) & 1) ? 51 : 0); }
    else p = 2652 + (j - 152);
    size_t posbase = (size_t)b * PROWS + p;
    uint4 z = {0, 0, 0, 0};
    ((uint4*)g_af)[posbase * 64 + which] = z;
}

// ============ 0a) features -> padded channel-last fp16 (coalesced) ============
__global__ __launch_bounds__(256) void prep_a_kernel(const float* __restrict__ feat) {
    __shared__ float t[32][53];
    int blk = blockIdx.x;
    int ci0 = (blk % 16) * 32;
    int h   = (blk / 16) % Hh;
    int b   = blk / (16 * Hh);
    int tx = threadIdx.x & 31, ty = threadIdx.x >> 5;
#pragma unroll
    for (int r = 0; r < 4; r++) {
        int ci = ci0 + ty + r * 8;
        const float* row = feat + ((size_t)(b * Cc + ci) * Hh + h) * Ww;
        t[ty + r * 8][tx] = row[tx];
        if (tx < 18) t[ty + r * 8][tx + 32] = row[tx + 32];
    }
    __syncthreads();
    size_t base = ((size_t)b * PROWS + (h + 1) * PADW + 1) * Cc + ci0;
#pragma unroll
    for (int r = 0; r < 7; r++) {
        int w = ty + r * 8;
        if (w < Ww)
            g_af[base + (size_t)w * Cc + tx] = __float2half(t[tx][w]);
    }
}

// ============ 0b) conv weights -> K-major fp16 ============
__global__ __launch_bounds__(256) void prep_b_kernel(const float* __restrict__ w1) {
    int idx = blockIdx.x * 256 + threadIdx.x;
    if (idx >= Cc * Kk) return;
    int k  = idx % Kk;
    int co = idx / Kk;
    int pos = k / Cc;
    int ci  = k % Cc;
    int kh = pos / 3, kw = pos % 3;
    g_bf[idx] = __float2half(w1[(((size_t)co * Cc + ci) * 3 + kh) * 3 + kw]);
}

// ============ 0c) head weights + anchors (merged) ============
__global__ __launch_bounds__(256) void misc_kernel(
    const float* __restrict__ w_cls, const float* __restrict__ w_box) {
    int idx = blockIdx.x * 256 + threadIdx.x;
    if (idx < 48 * Cc) {
        int c = idx % Cc;
        int o = idx / Cc;
        float v = 0.f;
        if (o < 9) v = w_cls[o * Cc + c];
        else if (o < 45) v = w_box[(o - 9) * Cc + c];
        g_wf[idx] = __float2half(v);
    } else {
        int n = idx - 48 * Cc;
        if (n < Nn) {
            float a0, a1, a2, a3;
            anchor_geom(n, &a0, &a1, &a2, &a3);
            g_anchor[n] = make_float4(a0, a1, a2, a3);
        }
    }
}

// ============ 1) conv implicit GEMM fp16, K=128/iter (256 thr, 2x4 warps) ============
__device__ __forceinline__ void conv_load_A2(
    uint32_t smb, int abuf, int grp, int p0, const __half* Af, int tid) {
    // grp = ci2*3 + kh ; rows cover padded raster [p0 + kh*PADW, +132), ci 128-wide
    uint32_t st = smb + abuf * A2_MAT;
    int ci0 = (grp / 3) * 128;
    int rbase = p0 + (grp % 3) * PADW;
#pragma unroll
    for (int i = 0; i < 9; i++) {
        int idx = tid + i * 256;
        if (idx < A2_ROWS * 16) {
            int m = idx >> 4, g = idx & 15;
            CP_ASYNC16(st + m * ASTRIDE + g * 16,
                       Af + ((size_t)(rbase + m) * Cc + ci0 + g * 8));
        }
    }
    CP_COMMIT();
}
__device__ __forceinline__ void conv_load_B2(
    uint32_t smb, int bbuf, int t, int co0, int tid) {
    uint32_t st = smb + 2 * A2_MAT + bbuf * B2_MAT;
    int grp = t / 3;
    int k0 = ((grp % 3) * 3 + (t % 3)) * 512 + (grp / 3) * 128;
#pragma unroll
    for (int i = 0; i < 8; i++) {
        int idx = tid + i * 256;
        int m = idx >> 4, g = idx & 15;
        CP_ASYNC16(st + m * ASTRIDE + g * 16,
                   g_bf + ((size_t)(co0 + m) * Kk + k0 + g * 8));
    }
    CP_COMMIT();
}

__global__ __launch_bounds__(256, 1) void conv_mma_kernel(const float* __restrict__ b1) {
    extern __shared__ __align__(128) char smc[];
    uint32_t smb = (uint32_t)__cvta_generic_to_shared(smc);
    int tid = threadIdx.x;
    int wid = tid >> 5;
    int lane = tid & 31;
    int p0  = blockIdx.x * 128;
    int co0 = blockIdx.y * 128;
    int b   = blockIdx.z;
    int warp_m = wid >> 2;    // 0..1 -> 64 rows
    int warp_n = wid & 3;     // 0..3 -> 32 cols

    const __half* Af = g_af + (size_t)b * PROWS * Cc;

    float acc[4][4][4];
#pragma unroll
    for (int i = 0; i < 4; i++)
#pragma unroll
        for (int j = 0; j < 4; j++)
#pragma unroll
            for (int k = 0; k < 4; k++) acc[i][j][k] = 0.f;

    conv_load_A2(smb, 0, 0, p0, Af, tid);
    conv_load_B2(smb, 0, 0, co0, tid);
    conv_load_B2(smb, 1, 1, co0, tid);

    int a_row = warp_m * 64 + (lane & 15);
    int a_col = (lane >> 4) << 3;
    int b_rowX4 = warp_n * 32 + (lane & 7) + ((lane >> 4) << 3);
    int b_colX4 = ((lane >> 3) & 1) << 3;

    for (int t = 0; t < 36; t++) {
        int grp = t / 3;          // ci2 = grp/3 (0..3), kh = grp%3
        int kw  = t % 3;
        if (t == 35) CP_WAIT0();
        else if (kw == 2 && grp < 11) CP_WAIT2();
        else CP_WAIT1();
        __syncthreads();

        uint32_t sA = smb + (grp & 1) * A2_MAT + (uint32_t)kw * ASTRIDE;
        uint32_t sB = smb + 2 * A2_MAT + (t % 3) * B2_MAT;

#pragma unroll
        for (int ks = 0; ks < 8; ks++) {
            uint32_t ah[4][4], bh[4][2];
#pragma unroll
            for (int mf = 0; mf < 4; mf++) {
                uint32_t off = (uint32_t)(a_row + mf * 16) * ASTRIDE + (a_col + ks * 16) * 2;
                LDSM_X4(ah[mf][0], ah[mf][1], ah[mf][2], ah[mf][3], sA + off);
            }
#pragma unroll
            for (int np = 0; np < 2; np++) {
                uint32_t off = (uint32_t)(b_rowX4 + np * 16) * ASTRIDE +
                               (b_colX4 + ks * 16) * 2;
                LDSM_X4(bh[2 * np][0], bh[2 * np][1],
                        bh[2 * np + 1][0], bh[2 * np + 1][1], sB + off);
            }
#pragma unroll
            for (int mf = 0; mf < 4; mf++)
#pragma unroll
                for (int nf = 0; nf < 4; nf++)
                    MMAF16(acc[mf][nf], ah[mf], bh[nf]);
        }
        // no trailing sync: prefetches write slots not read in iters t, t+1
        if (kw == 1 && grp < 11)
            conv_load_A2(smb, (grp + 1) & 1, grp + 1, p0, Af, tid);
        if (t + 2 < 36)
            conv_load_B2(smb, (t + 2) % 3, t + 2, co0, tid);
    }

    // epilogue: +bias -> fp16 x, channel-last
#pragma unroll
    for (int nf = 0; nf < 4; nf++) {
        int colg = co0 + warp_n * 32 + nf * 8 + (lane & 3) * 2;
        float bv0 = __ldg(&b1[colg]);
        float bv1 = __ldg(&b1[colg + 1]);
#pragma unroll
        for (int mf = 0; mf < 4; mf++) {
            int row0 = p0 + warp_m * 64 + mf * 16 + (lane >> 2);
#pragma unroll
            for (int half = 0; half < 2; half++) {
                int p = row0 + half * 8;
                int h = p / PADW, w = p % PADW;
                if (h < Hh && w < Ww) {
                    __half2 v;
                    v.x = __float2half(acc[mf][nf][half * 2 + 0] + bv0);
                    v.y = __float2half(acc[mf][nf][half * 2 + 1] + bv1);
                    size_t off = ((size_t)((b * Hh + h) * Ww + w)) * Cc + colg;
                    *(__half2*)&g_xf[off] = v;
                }
            }
        }
    }
}

// ============ 2) heads as fp16 MMA GEMM: [40000 x 512] x [512 x 48] ============
__device__ __forceinline__ void head_load_chunk(uint32_t smb, int stage, int kc,
                                                int p0, int tid) {
    uint32_t st = smb + stage * H_AST;
#pragma unroll
    for (int i = 0; i < 8; i++) {
        int idx = tid + i * 128;
        int r = idx >> 3;
        int g = idx & 7;
        const __half* src = g_xf + ((size_t)(p0 + r) * Cc + kc * 64 + g * 8);
        CP_ASYNC16(st + r * 144 + g * 16, src);
    }
}

__global__ __launch_bounds__(128, 1) void head_mma_kernel(
    const float* __restrict__ b_cls, const float* __restrict__ b_box) {
    extern __shared__ __align__(128) char smc[];
    uint32_t smb = (uint32_t)__cvta_generic_to_shared(smc);
    uint32_t smW = smb + 3 * H_AST;
    int tid = threadIdx.x;
    int wid = tid >> 5;
    int lane = tid & 31;
    int p0 = blockIdx.x * 128;

    {
#pragma unroll
        for (int i = 0; i < 24; i++) {
            int linear = tid + i * 128;
            int row = linear / 64;
            int gc = linear % 64;
            const __half* src = g_wf + (size_t)row * Cc + gc * 8;
            CP_ASYNC16(smW + row * H_WSTRIDE + gc * 16, src);
        }
        head_load_chunk(smb, 0, 0, p0, tid);
        CP_COMMIT();
    }
    head_load_chunk(smb, 1, 1, p0, tid);
    CP_COMMIT();

    float acc[2][6][4];
#pragma unroll
    for (int i = 0; i < 2; i++)
#pragma unroll
        for (int j = 0; j < 6; j++)
#pragma unroll
            for (int k = 0; k < 4; k++) acc[i][j][k] = 0.f;

    int a_row = wid * 32 + (lane & 15);
    int a_col = (lane >> 4) << 3;
    int b_row = lane & 7;
    int b_col = ((lane >> 3) & 1) << 3;

    for (int kc = 0; kc < H_CHUNKS; kc++) {
        int s = kc % 3;
        if (kc + 2 < H_CHUNKS) {
            CP_WAIT1();
            __syncthreads();
            head_load_chunk(smb, (kc + 2) % 3, kc + 2, p0, tid);
            CP_COMMIT();
        } else if (kc + 1 < H_CHUNKS) {
            CP_WAIT1();
            __syncthreads();
        } else {
            CP_WAIT0();
            __syncthreads();
        }
        uint32_t sA = smb + s * H_AST;
#pragma unroll
        for (int ks = 0; ks < 4; ks++) {
            uint32_t ah[2][4], bh[6][2];
#pragma unroll
            for (int mf = 0; mf < 2; mf++) {
                uint32_t off = (uint32_t)(a_row + mf * 16) * 144 + (a_col + ks * 16) * 2;
                LDSM_X4(ah[mf][0], ah[mf][1], ah[mf][2], ah[mf][3], sA + off);
            }
#pragma unroll
            for (int nf = 0; nf < 6; nf++) {
                uint32_t off = (uint32_t)(b_row + nf * 8) * H_WSTRIDE +
                               (kc * 64 + b_col + ks * 16) * 2;
                LDSM_X2(bh[nf][0], bh[nf][1], smW + off);
            }
#pragma unroll
            for (int mf = 0; mf < 2; mf++)
#pragma unroll
                for (int nf = 0; nf < 6; nf++)
                    MMAF16(acc[mf][nf], ah[mf], bh[nf]);
        }
    }

#pragma unroll
    for (int nf = 0; nf < 6; nf++) {
        int o0 = nf * 8 + (lane & 3) * 2;
#pragma unroll
        for (int mf = 0; mf < 2; mf++) {
            int row0 = p0 + wid * 32 + mf * 16 + (lane >> 2);
#pragma unroll
            for (int half = 0; half < 2; half++) {
                int pix = row0 + half * 8;
                if (pix < Bn * Hh * Ww) {
                    int b = pix / (Hh * Ww);
                    int hw = pix % (Hh * Ww);
#pragma unroll
                    for (int q = 0; q < 2; q++) {
                        int o = o0 + q;
                        if (o < 45) {
                            float v = acc[mf][nf][half * 2 + q];
                            if (o < 9) {
                                v += __ldg(&b_cls[o]);
                                g_logits[b * Nn + hw * Aa + o] = v;
                            } else {
                                int d = o - 9;
                                v += __ldg(&b_box[d]);
                                g_pred[((size_t)(b * Nn + hw * Aa + d / 4)) * 4 + (d & 3)] = v;
                            }
                        }
                    }
                }
            }
        }
    }
}

// ============ 3) max IoU per (b, gt) ============
__global__ __launch_bounds__(256) void maxiou_kernel(const float* __restrict__ gt_boxes) {
    int bm = blockIdx.x;
    float gx1 = gt_boxes[bm * 4 + 0] * 0.0625f;
    float gy1 = gt_boxes[bm * 4 + 1] * 0.0625f;
    float gx2 = gt_boxes[bm * 4 + 2] * 0.0625f;
    float gy2 = gt_boxes[bm * 4 + 3] * 0.0625f;
    float mx = -1.f;
    for (int n = threadIdx.x; n < Nn; n += 256) {
        float4 a = g_anchor[n];
        float v = iou_fn(a.x, a.y, a.z, a.w, gx1, gy1, gx2, gy2);
        mx = fmaxf(mx, v);
    }
    __shared__ float sm[256];
    sm[threadIdx.x] = mx;
    __syncthreads();
    for (int s = 128; s; s >>= 1) {
        if (threadIdx.x < s) sm[threadIdx.x] = fmaxf(sm[threadIdx.x], sm[threadIdx.x + s]);
        __syncthreads();
    }
    if (threadIdx.x == 0) g_maxiou[bm] = sm[0];
}

// ============ 4) per-anchor losses -> block partials ============
__global__ __launch_bounds__(256) void loss_kernel(const float* __restrict__ gt_boxes) {
    int gid = blockIdx.x * 256 + threadIdx.x;
    float v_npos = 0.f, v_reg = 0.f, v_pos = 0.f, v_neg = 0.f, v_nneg = 0.f;
    if (gid < Bn * Nn) {
        int b = gid / Nn;
        int n = gid % Nn;
        float4 anc = g_anchor[n];
        float ax1 = anc.x, ay1 = anc.y, ax2 = anc.z, ay2 = anc.w;
        float acx = (ax1 + ax2) * 0.5f, acy = (ay1 + ay2) * 0.5f;
        float aw = fmaxf(ax2 - ax1, 1e-6f), ah = fmaxf(ay2 - ay1, 1e-6f);
        float p0 = g_pred[(size_t)gid * 4 + 0];
        float p1 = g_pred[(size_t)gid * 4 + 1];
        float p2 = g_pred[(size_t)gid * 4 + 2];
        float p3 = g_pred[(size_t)gid * 4 + 3];
        float logit = g_logits[gid];
        bool allneg = true;
        float pm_sum = 0.f;
        for (int m = 0; m < Mm; m++) {
            float gx1 = gt_boxes[(b * Mm + m) * 4 + 0] * 0.0625f;
            float gy1 = gt_boxes[(b * Mm + m) * 4 + 1] * 0.0625f;
            float gx2 = gt_boxes[(b * Mm + m) * 4 + 2] * 0.0625f;
            float gy2 = gt_boxes[(b * Mm + m) * 4 + 3] * 0.0625f;
            float v = iou_fn(ax1, ay1, ax2, ay2, gx1, gy1, gx2, gy2);
            float mxv = g_maxiou[b * Mm + m];
            bool pmask = ((v == mxv) && (mxv > 0.f)) || (v > 0.7f);
            if (!(v < 0.3f)) allneg = false;
            if (pmask) {
                pm_sum += 1.f;
                float gcx = (gx1 + gx2) * 0.5f, gcy = (gy1 + gy2) * 0.5f;
                float gw = fmaxf(gx2 - gx1, 1e-6f), gh = fmaxf(gy2 - gy1, 1e-6f);
                float tx = (gcx - acx) / aw;
                float ty = (gcy - acy) / ah;
                float tw = logf(gw / aw);
                float th = logf(gh / ah);
                v_reg += sl1(tx - p0) + sl1(ty - p1) + sl1(tw - p2) + sl1(th - p3);
            }
        }
        v_npos = pm_sum;
        v_pos = pm_sum * softplus_f(-logit);
        if (allneg) { v_nneg = 1.f; v_neg = softplus_f(logit); }
    }
    __shared__ float rs[256];
    float vals[5] = {v_npos, v_reg, v_pos, v_neg, v_nneg};
#pragma unroll
    for (int k = 0; k < 5; k++) {
        rs[threadIdx.x] = vals[k];
        __syncthreads();
        for (int s = 128; s; s >>= 1) {
            if (threadIdx.x < s) rs[threadIdx.x] += rs[threadIdx.x + s];
            __syncthreads();
        }
        if (threadIdx.x == 0) g_part[blockIdx.x * 5 + k] = rs[0];
        __syncthreads();
    }
}

// ============ 5) finalize scalar loss ============
__global__ __launch_bounds__(256) void finalize_kernel(float* __restrict__ out) {
    float loc[5] = {0.f, 0.f, 0.f, 0.f, 0.f};
    for (int i = threadIdx.x; i < LOSS_BLOCKS; i += 256) {
#pragma unroll
        for (int k = 0; k < 5; k++) loc[k] += g_part[i * 5 + k];
    }
    __shared__ float sm[256];
    float tot[5];
#pragma unroll
    for (int k = 0; k < 5; k++) {
        sm[threadIdx.x] = loc[k];
        __syncthreads();
        for (int s = 128; s; s >>= 1) {
            if (threadIdx.x < s) sm[threadIdx.x] += sm[threadIdx.x + s];
            __syncthreads();
        }
        tot[k] = sm[0];
        __syncthreads();
    }
    if (threadIdx.x == 0) {
        float n_pos = fmaxf(tot[0], 1.f);
        float n_neg = fmaxf(tot[4], 1.f);
        float reg_loss = tot[1] / (4.f * n_pos);
        float cls_loss = 0.5f * (tot[2] / n_pos + tot[3] / n_neg);
        out[0] = 1.0f * cls_loss + 5.0f * reg_loss;
    }
}

// ============ 6) proposals ============
__global__ __launch_bounds__(256) void proposal_kernel(float* __restrict__ out, int base) {
    int gid = blockIdx.x * 256 + threadIdx.x;
    if (gid >= Bn * Nn) return;
    int n = gid % Nn;
    float4 anc = g_anchor[n];
    float acx = (anc.x + anc.z) * 0.5f, acy = (anc.y + anc.w) * 0.5f;
    float aw = fmaxf(anc.z - anc.x, 1e-6f), ah = fmaxf(anc.w - anc.y, 1e-6f);
    float p0 = g_pred[(size_t)gid * 4 + 0];
    float p1 = g_pred[(size_t)gid * 4 + 1];
    float p2 = g_pred[(size_t)gid * 4 + 2];
    float p3 = g_pred[(size_t)gid * 4 + 3];
    float pcx = acx + p0 * aw;
    float pcy = acy + p1 * ah;
    float pw = aw * expf(p2);
    float ph = ah * expf(p3);
    out[base + (size_t)gid * 4 + 0] = pcx - pw * 0.5f;
    out[base + (size_t)gid * 4 + 1] = pcy - ph * 0.5f;
    out[base + (size_t)gid * 4 + 2] = pcx + pw * 0.5f;
    out[base + (size_t)gid * 4 + 3] = pcy + ph * 0.5f;
}

extern "C" void kernel_launch(void* const* d_in, const int* in_sizes, int n_in,
                              void* d_out, int out_size) {
    const float* features = (const float*)d_in[0];
    const float* gt_boxes = (const float*)d_in[1];
    const float* w1       = (const float*)d_in[2];
    const float* b1       = (const float*)d_in[3];
    const float* w_cls    = (const float*)d_in[4];
    const float* b_cls    = (const float*)d_in[5];
    const float* w_box    = (const float*)d_in[6];
    const float* b_box    = (const float*)d_in[7];
    float* out = (float*)d_out;

    int base = out_size - Bn * Nn * 4;
    if (base < 0) base = 0;

    cudaFuncSetAttribute(conv_mma_kernel, cudaFuncAttributeMaxDynamicSharedMemorySize, DYN_SMEM);
    cudaFuncSetAttribute(head_mma_kernel, cudaFuncAttributeMaxDynamicSharedMemorySize, H_SMEM);

    int zitems = Bn * 316 * 64;
    zero_pad_kernel<<<(zitems + 255) / 256, 256>>>();
    prep_a_kernel<<<Bn * Hh * 16, 256>>>(features);
    prep_b_kernel<<<(Cc * Kk + 255) / 256, 256>>>(w1);
    conv_mma_kernel<<<dim3(PTILES, NTILES, Bn), 256, DYN_SMEM>>>(b1);
    misc_kernel<<<(48 * Cc + Nn + 255) / 256, 256>>>(w_cls, w_box);
    head_mma_kernel<<<(Bn * Hh * Ww + 127) / 128, 128, H_SMEM>>>(b_cls, b_box);
    maxiou_kernel<<<Bn * Mm, 256>>>(gt_boxes);
    loss_kernel<<<LOSS_BLOCKS, 256>>>(gt_boxes);
    finalize_kernel<<<1, 256>>>(out);
    proposal_kernel<<<LOSS_BLOCKS, 256>>>(out, base);
}

// round 13
// speedup vs baseline: 1.1230x; 1.1230x over previous
#include <cuda_runtime.h>
#include <cuda_fp16.h>
#include <math.h>
#include <stdint.h>

#define Bn 16
#define Cc 512
#define Hh 50
#define Ww 50
#define Aa 9
#define Nn (Hh*Ww*Aa)   // 22500
#define Mm 16
#define LOSS_BLOCKS ((Bn*Nn + 255)/256)  // 1407

#define PADW 52
#define PROWS 2816
#define Kk 4608
#define PTILES 21
#define NTILES 4

// conv smem: A per-(ci,kh) tile 132 rows x 64ci fp16, 2 stages;
//            B tile 128 co x 64 ci fp16, 3 stages. Row stride 144B.
#define B_MAT 18432                   // 128*144
#define A2_ROWS 132
#define A2_MAT 19072                  // 132*144 = 19008 pad
#define DYN_SMEM (2*A2_MAT + 3*B_MAT) // 93440  -> 2 CTAs/SM

// head GEMM: M=40192, N=48, K=512, fp16 single pass
#define HROWS 40192
#define H_AST 18432                   // 128*144 per stage
#define H_WSTRIDE 1040
#define H_WBYTES (48*H_WSTRIDE)       // 49920
#define H_SMEM (3*H_AST + H_WBYTES)   // 105216
#define H_CHUNKS 8

// -------- scratch --------
__device__ float g_logits[Bn*Nn];
__device__ float g_pred[Bn*Nn*4];
__device__ float g_maxiou[Bn*Mm];
__device__ float g_part[LOSS_BLOCKS*5];
__device__ float4 g_anchor[Nn];
__device__ __align__(16) __half g_af[(size_t)Bn*PROWS*Cc];
__device__ __align__(16) __half g_bf[(size_t)Cc*Kk];
__device__ __align__(16) __half g_xf[(size_t)HROWS*Cc];
__device__ __align__(16) __half g_wf[48*Cc];

// ============ PTX helpers ============
#define CP_ASYNC16(dst, src) \
    asm volatile("cp.async.cg.shared.global [%0], [%1], 16;" :: "r"(dst), "l"(src))
#define CP_COMMIT() asm volatile("cp.async.commit_group;" ::: "memory")
#define CP_WAIT2()  asm volatile("cp.async.wait_group 2;" ::: "memory")
#define CP_WAIT1()  asm volatile("cp.async.wait_group 1;" ::: "memory")
#define CP_WAIT0()  asm volatile("cp.async.wait_group 0;" ::: "memory")

#define LDSM_X4(r0, r1, r2, r3, addr) \
    asm volatile("ldmatrix.sync.aligned.m8n8.x4.shared.b16 {%0,%1,%2,%3}, [%4];" \
        : "=r"(r0), "=r"(r1), "=r"(r2), "=r"(r3) : "r"(addr))
#define LDSM_X2(r0, r1, addr) \
    asm volatile("ldmatrix.sync.aligned.m8n8.x2.shared.b16 {%0,%1}, [%2];" \
        : "=r"(r0), "=r"(r1) : "r"(addr))

#define MMAF16(d, a, b) \
    asm volatile("mma.sync.aligned.m16n8k16.row.col.f32.f16.f16.f32 " \
        "{%0,%1,%2,%3}, {%4,%5,%6,%7}, {%8,%9}, {%0,%1,%2,%3};" \
        : "+f"((d)[0]), "+f"((d)[1]), "+f"((d)[2]), "+f"((d)[3]) \
        : "r"((a)[0]), "r"((a)[1]), "r"((a)[2]), "r"((a)[3]), "r"((b)[0]), "r"((b)[1]))

// ============ shared math helpers ============
__device__ __forceinline__ void anchor_geom(int n, float* ax1, float* ay1, float* ax2, float* ay2) {
    int a  = n % Aa;
    int i1 = (n / Aa) % Hh;
    int i0 = n / (Aa * Hh);
    const float SC[3] = {2.f, 4.f, 6.f};
    const float RA[3] = {0.5f, 1.f, 1.5f};
    float ws = SC[a % 3] * RA[a / 3];
    float hs = SC[a % 3];
    float cx = (float)i0 + 0.5f;
    float cy = (float)i1 + 0.5f;
    *ax1 = fminf(fmaxf(cx - ws * 0.5f, 0.f), 50.f);
    *ax2 = fminf(fmaxf(cx + ws * 0.5f, 0.f), 50.f);
    *ay1 = fminf(fmaxf(cy - hs * 0.5f, 0.f), 50.f);
    *ay2 = fminf(fmaxf(cy + hs * 0.5f, 0.f), 50.f);
}
// noinline: maxiou and loss must produce bitwise-identical iou values
__device__ __noinline__ float iou_fn(float ax1, float ay1, float ax2, float ay2,
                                     float gx1, float gy1, float gx2, float gy2) {
    float ix1 = fmaxf(ax1, gx1);
    float iy1 = fmaxf(ay1, gy1);
    float ix2 = fminf(ax2, gx2);
    float iy2 = fminf(ay2, gy2);
    float iw = fmaxf(ix2 - ix1, 0.f);
    float ih = fmaxf(iy2 - iy1, 0.f);
    float inter = iw * ih;
    float aa = (ax2 - ax1) * (ay2 - ay1);
    float ag = (gx2 - gx1) * (gy2 - gy1);
    return inter / (aa + ag - inter + 1e-8f);
}
__device__ __forceinline__ float softplus_f(float x) {
    return fmaxf(x, 0.f) + log1pf(expf(-fabsf(x)));
}
__device__ __forceinline__ float sl1(float d) {
    float a = fabsf(d);
    return (a < 1.f) ? 0.5f * d * d : a - 0.5f;
}

// ============ 0) zero the padding positions of the A slab ============
__global__ __launch_bounds__(256) void zero_pad_kernel() {
    int idx = blockIdx.x * 256 + threadIdx.x;
    const int PER = 64;
    int pos_id = idx / PER;
    int which = idx % PER;
    if (pos_id >= Bn * 316) return;
    int b = pos_id / 316;
    int j = pos_id % 316;
    int p;
    if (j < 52) p = j;
    else if (j < 152) { int r = 1 + (j - 52) / 2; p = r * PADW + (((j - 52) & 1) ? 51 : 0); }
    else p = 2652 + (j - 152);
    size_t posbase = (size_t)b * PROWS + p;
    uint4 z = {0, 0, 0, 0};
    ((uint4*)g_af)[posbase * 64 + which] = z;
}

// ============ 0a) features -> padded channel-last fp16 (coalesced) ============
__global__ __launch_bounds__(256) void prep_a_kernel(const float* __restrict__ feat) {
    __shared__ float t[32][53];
    int blk = blockIdx.x;
    int ci0 = (blk % 16) * 32;
    int h   = (blk / 16) % Hh;
    int b   = blk / (16 * Hh);
    int tx = threadIdx.x & 31, ty = threadIdx.x >> 5;
#pragma unroll
    for (int r = 0; r < 4; r++) {
        int ci = ci0 + ty + r * 8;
        const float* row = feat + ((size_t)(b * Cc + ci) * Hh + h) * Ww;
        t[ty + r * 8][tx] = row[tx];
        if (tx < 18) t[ty + r * 8][tx + 32] = row[tx + 32];
    }
    __syncthreads();
    size_t base = ((size_t)b * PROWS + (h + 1) * PADW + 1) * Cc + ci0;
#pragma unroll
    for (int r = 0; r < 7; r++) {
        int w = ty + r * 8;
        if (w < Ww)
            g_af[base + (size_t)w * Cc + tx] = __float2half(t[tx][w]);
    }
}

// ============ 0b) conv weights -> K-major fp16 (coalesced via smem) ============
// block handles 2 co rows; w1[co] is 4608 contiguous floats.
__global__ __launch_bounds__(256) void prep_b_kernel(const float* __restrict__ w1) {
    __shared__ float t[2 * Kk];
    int co0 = blockIdx.x * 2;
    int tid = threadIdx.x;
    const float* src = w1 + (size_t)co0 * Kk;
#pragma unroll
    for (int i = 0; i < 36; i++)
        t[tid + i * 256] = src[tid + i * 256];
    __syncthreads();
    // write: (co, pos, ci) with ci fastest -> coalesced g_bf writes
#pragma unroll
    for (int i = 0; i < 36; i++) {
        int idx = tid + i * 256;          // < 9216
        int c  = idx >> 12;               // 0..1 (4096-sized halves? no: use /4608)
        // careful: 9216 = 2*4608; recompute cleanly:
        c = idx / Kk;
        int r = idx - c * Kk;             // 0..4607 = pos*512 + ci
        int pos = r >> 9;
        int ci  = r & 511;
        // t layout: co row c at [c*Kk + ci*9 + pos]
        g_bf[(size_t)(co0 + c) * Kk + r] = __float2half(t[c * Kk + ci * 9 + pos]);
    }
}

// ============ 0c) head weights + anchors (merged) ============
__global__ __launch_bounds__(256) void misc_kernel(
    const float* __restrict__ w_cls, const float* __restrict__ w_box) {
    int idx = blockIdx.x * 256 + threadIdx.x;
    if (idx < 48 * Cc) {
        int c = idx % Cc;
        int o = idx / Cc;
        float v = 0.f;
        if (o < 9) v = w_cls[o * Cc + c];
        else if (o < 45) v = w_box[(o - 9) * Cc + c];
        g_wf[idx] = __float2half(v);
    } else {
        int n = idx - 48 * Cc;
        if (n < Nn) {
            float a0, a1, a2, a3;
            anchor_geom(n, &a0, &a1, &a2, &a3);
            g_anchor[n] = make_float4(a0, a1, a2, a3);
        }
    }
}

// ============ 1) conv implicit GEMM fp16 single-pass (256 thr, 2x4 warps) ============
__device__ __forceinline__ void conv_load_A2(
    uint32_t smb, int abuf, int grp, int p0, const __half* Af, int tid) {
    uint32_t st = smb + abuf * A2_MAT;
    int ci0 = (grp / 3) * 64;
    int rbase = p0 + (grp % 3) * PADW;
#pragma unroll
    for (int i = 0; i < 5; i++) {
        int idx = tid + i * 256;
        if (idx < A2_ROWS * 8) {
            int m = idx >> 3, g = idx & 7;
            CP_ASYNC16(st + m * 144 + g * 16, Af + ((size_t)(rbase + m) * Cc + ci0 + g * 8));
        }
    }
    CP_COMMIT();
}
__device__ __forceinline__ void conv_load_B2(
    uint32_t smb, int bbuf, int t, int co0, int tid) {
    uint32_t st = smb + 2 * A2_MAT + bbuf * B_MAT;
    int k0 = (t % 9) * 512 + (t / 9) * 64;
#pragma unroll
    for (int i = 0; i < 4; i++) {
        int idx = tid + i * 256;
        int m = idx >> 3, g = idx & 7;
        CP_ASYNC16(st + m * 144 + g * 16, g_bf + ((size_t)(co0 + m) * Kk + k0 + g * 8));
    }
    CP_COMMIT();
}

__global__ __launch_bounds__(256, 2) void conv_mma_kernel(const float* __restrict__ b1) {
    extern __shared__ __align__(128) char smc[];
    uint32_t smb = (uint32_t)__cvta_generic_to_shared(smc);
    int tid = threadIdx.x;
    int wid = tid >> 5;
    int lane = tid & 31;
    int p0  = blockIdx.x * 128;
    int co0 = blockIdx.y * 128;
    int b   = blockIdx.z;
    int warp_m = wid >> 2;    // 0..1 -> 64 rows
    int warp_n = wid & 3;     // 0..3 -> 32 cols

    const __half* Af = g_af + (size_t)b * PROWS * Cc;

    float acc[4][4][4];
#pragma unroll
    for (int i = 0; i < 4; i++)
#pragma unroll
        for (int j = 0; j < 4; j++)
#pragma unroll
            for (int k = 0; k < 4; k++) acc[i][j][k] = 0.f;

    conv_load_A2(smb, 0, 0, p0, Af, tid);
    conv_load_B2(smb, 0, 0, co0, tid);
    conv_load_B2(smb, 1, 1, co0, tid);

    int a_row = warp_m * 64 + (lane & 15);
    int a_col = (lane >> 4) << 3;
    int b_rowX4 = warp_n * 32 + (lane & 7) + ((lane >> 4) << 3);
    int b_colX4 = ((lane >> 3) & 1) << 3;

    for (int t = 0; t < 72; t++) {
        int grp = t / 3;          // ci = grp/3, kh = grp%3
        int kw  = t % 3;
        if (t == 71) CP_WAIT0();
        else if (kw == 2 && grp < 23) CP_WAIT2();
        else CP_WAIT1();
        __syncthreads();

        uint32_t sA = smb + (grp & 1) * A2_MAT + (uint32_t)kw * 144;
        uint32_t sB = smb + 2 * A2_MAT + (t % 3) * B_MAT;

#pragma unroll
        for (int ks = 0; ks < 4; ks++) {
            uint32_t ah[4][4], bh[4][2];
#pragma unroll
            for (int mf = 0; mf < 4; mf++) {
                uint32_t off = (uint32_t)(a_row + mf * 16) * 144 + (a_col + ks * 16) * 2;
                LDSM_X4(ah[mf][0], ah[mf][1], ah[mf][2], ah[mf][3], sA + off);
            }
#pragma unroll
            for (int np = 0; np < 2; np++) {
                uint32_t off = (uint32_t)(b_rowX4 + np * 16) * 144 +
                               (b_colX4 + ks * 16) * 2;
                LDSM_X4(bh[2 * np][0], bh[2 * np][1],
                        bh[2 * np + 1][0], bh[2 * np + 1][1], sB + off);
            }
#pragma unroll
            for (int mf = 0; mf < 4; mf++)
#pragma unroll
                for (int nf = 0; nf < 4; nf++)
                    MMAF16(acc[mf][nf], ah[mf], bh[nf]);
        }
        if (kw == 1 && grp < 23)
            conv_load_A2(smb, (grp + 1) & 1, grp + 1, p0, Af, tid);
        if (t + 2 < 72) {
            int tn = t + 2;
            int gn = tn / 3, kn = tn % 3;
            int tt = (gn / 3) * 9 + (gn % 3) * 3 + kn;
            conv_load_B2(smb, tn % 3, tt, co0, tid);
        }
    }

    // epilogue: +bias -> fp16 x, channel-last
#pragma unroll
    for (int nf = 0; nf < 4; nf++) {
        int colg = co0 + warp_n * 32 + nf * 8 + (lane & 3) * 2;
        float bv0 = __ldg(&b1[colg]);
        float bv1 = __ldg(&b1[colg + 1]);
#pragma unroll
        for (int mf = 0; mf < 4; mf++) {
            int row0 = p0 + warp_m * 64 + mf * 16 + (lane >> 2);
#pragma unroll
            for (int half = 0; half < 2; half++) {
                int p = row0 + half * 8;
                int h = p / PADW, w = p % PADW;
                if (h < Hh && w < Ww) {
                    __half2 v;
                    v.x = __float2half(acc[mf][nf][half * 2 + 0] + bv0);
                    v.y = __float2half(acc[mf][nf][half * 2 + 1] + bv1);
                    size_t off = ((size_t)((b * Hh + h) * Ww + w)) * Cc + colg;
                    *(__half2*)&g_xf[off] = v;
                }
            }
        }
    }
}

// ============ 2) heads as fp16 MMA GEMM ============
__device__ __forceinline__ void head_load_chunk(uint32_t smb, int stage, int kc,
                                                int p0, int tid) {
    uint32_t st = smb + stage * H_AST;
#pragma unroll
    for (int i = 0; i < 8; i++) {
        int idx = tid + i * 128;
        int r = idx >> 3;
        int g = idx & 7;
        const __half* src = g_xf + ((size_t)(p0 + r) * Cc + kc * 64 + g * 8);
        CP_ASYNC16(st + r * 144 + g * 16, src);
    }
}

__global__ __launch_bounds__(128, 1) void head_mma_kernel(
    const float* __restrict__ b_cls, const float* __restrict__ b_box) {
    extern __shared__ __align__(128) char smc[];
    uint32_t smb = (uint32_t)__cvta_generic_to_shared(smc);
    uint32_t smW = smb + 3 * H_AST;
    int tid = threadIdx.x;
    int wid = tid >> 5;
    int lane = tid & 31;
    int p0 = blockIdx.x * 128;

    {
#pragma unroll
        for (int i = 0; i < 24; i++) {
            int linear = tid + i * 128;
            int row = linear / 64;
            int gc = linear % 64;
            const __half* src = g_wf + (size_t)row * Cc + gc * 8;
            CP_ASYNC16(smW + row * H_WSTRIDE + gc * 16, src);
        }
        head_load_chunk(smb, 0, 0, p0, tid);
        CP_COMMIT();
    }
    head_load_chunk(smb, 1, 1, p0, tid);
    CP_COMMIT();

    float acc[2][6][4];
#pragma unroll
    for (int i = 0; i < 2; i++)
#pragma unroll
        for (int j = 0; j < 6; j++)
#pragma unroll
            for (int k = 0; k < 4; k++) acc[i][j][k] = 0.f;

    int a_row = wid * 32 + (lane & 15);
    int a_col = (lane >> 4) << 3;
    int b_row = lane & 7;
    int b_col = ((lane >> 3) & 1) << 3;

    for (int kc = 0; kc < H_CHUNKS; kc++) {
        int s = kc % 3;
        if (kc + 2 < H_CHUNKS) {
            CP_WAIT1();
            __syncthreads();
            head_load_chunk(smb, (kc + 2) % 3, kc + 2, p0, tid);
            CP_COMMIT();
        } else if (kc + 1 < H_CHUNKS) {
            CP_WAIT1();
            __syncthreads();
        } else {
            CP_WAIT0();
            __syncthreads();
        }
        uint32_t sA = smb + s * H_AST;
#pragma unroll
        for (int ks = 0; ks < 4; ks++) {
            uint32_t ah[2][4], bh[6][2];
#pragma unroll
            for (int mf = 0; mf < 2; mf++) {
                uint32_t off = (uint32_t)(a_row + mf * 16) * 144 + (a_col + ks * 16) * 2;
                LDSM_X4(ah[mf][0], ah[mf][1], ah[mf][2], ah[mf][3], sA + off);
            }
#pragma unroll
            for (int nf = 0; nf < 6; nf++) {
                uint32_t off = (uint32_t)(b_row + nf * 8) * H_WSTRIDE +
                               (kc * 64 + b_col + ks * 16) * 2;
                LDSM_X2(bh[nf][0], bh[nf][1], smW + off);
            }
#pragma unroll
            for (int mf = 0; mf < 2; mf++)
#pragma unroll
                for (int nf = 0; nf < 6; nf++)
                    MMAF16(acc[mf][nf], ah[mf], bh[nf]);
        }
    }

#pragma unroll
    for (int nf = 0; nf < 6; nf++) {
        int o0 = nf * 8 + (lane & 3) * 2;
#pragma unroll
        for (int mf = 0; mf < 2; mf++) {
            int row0 = p0 + wid * 32 + mf * 16 + (lane >> 2);
#pragma unroll
            for (int half = 0; half < 2; half++) {
                int pix = row0 + half * 8;
                if (pix < Bn * Hh * Ww) {
                    int b = pix / (Hh * Ww);
                    int hw = pix % (Hh * Ww);
#pragma unroll
                    for (int q = 0; q < 2; q++) {
                        int o = o0 + q;
                        if (o < 45) {
                            float v = acc[mf][nf][half * 2 + q];
                            if (o < 9) {
                                v += __ldg(&b_cls[o]);
                                g_logits[b * Nn + hw * Aa + o] = v;
                            } else {
                                int d = o - 9;
                                v += __ldg(&b_box[d]);
                                g_pred[((size_t)(b * Nn + hw * Aa + d / 4)) * 4 + (d & 3)] = v;
                            }
                        }
                    }
                }
            }
        }
    }
}

// ============ 3) max IoU per (b, gt) ============
__global__ __launch_bounds__(256) void maxiou_kernel(const float* __restrict__ gt_boxes) {
    int bm = blockIdx.x;
    float gx1 = gt_boxes[bm * 4 + 0] * 0.0625f;
    float gy1 = gt_boxes[bm * 4 + 1] * 0.0625f;
    float gx2 = gt_boxes[bm * 4 + 2] * 0.0625f;
    float gy2 = gt_boxes[bm * 4 + 3] * 0.0625f;
    float mx = -1.f;
    for (int n = threadIdx.x; n < Nn; n += 256) {
        float4 a = g_anchor[n];
        float v = iou_fn(a.x, a.y, a.z, a.w, gx1, gy1, gx2, gy2);
        mx = fmaxf(mx, v);
    }
    __shared__ float sm[256];
    sm[threadIdx.x] = mx;
    __syncthreads();
    for (int s = 128; s; s >>= 1) {
        if (threadIdx.x < s) sm[threadIdx.x] = fmaxf(sm[threadIdx.x], sm[threadIdx.x + s]);
        __syncthreads();
    }
    if (threadIdx.x == 0) g_maxiou[bm] = sm[0];
}

// ============ 4) per-anchor losses + proposals (fused) ============
__global__ __launch_bounds__(256) void loss_kernel(const float* __restrict__ gt_boxes,
                                                   float* __restrict__ out, int base) {
    __shared__ float gts[Bn * Mm * 4];   // all gt boxes, pre-scaled
    __shared__ float mxs[Bn * Mm];
    for (int i = threadIdx.x; i < Bn * Mm * 4; i += 256) gts[i] = gt_boxes[i] * 0.0625f;
    for (int i = threadIdx.x; i < Bn * Mm; i += 256) mxs[i] = g_maxiou[i];
    __syncthreads();

    int gid = blockIdx.x * 256 + threadIdx.x;
    float v_npos = 0.f, v_reg = 0.f, v_pos = 0.f, v_neg = 0.f, v_nneg = 0.f;
    if (gid < Bn * Nn) {
        int b = gid / Nn;
        int n = gid % Nn;
        float4 anc = g_anchor[n];
        float ax1 = anc.x, ay1 = anc.y, ax2 = anc.z, ay2 = anc.w;
        float acx = (ax1 + ax2) * 0.5f, acy = (ay1 + ay2) * 0.5f;
        float aw = fmaxf(ax2 - ax1, 1e-6f), ah = fmaxf(ay2 - ay1, 1e-6f);
        float p0 = g_pred[(size_t)gid * 4 + 0];
        float p1 = g_pred[(size_t)gid * 4 + 1];
        float p2 = g_pred[(size_t)gid * 4 + 2];
        float p3 = g_pred[(size_t)gid * 4 + 3];
        float logit = g_logits[gid];
        bool allneg = true;
        float pm_sum = 0.f;
        for (int m = 0; m < Mm; m++) {
            int bm = b * Mm + m;
            float gx1 = gts[bm * 4 + 0];
            float gy1 = gts[bm * 4 + 1];
            float gx2 = gts[bm * 4 + 2];
            float gy2 = gts[bm * 4 + 3];
            float v = iou_fn(ax1, ay1, ax2, ay2, gx1, gy1, gx2, gy2);
            float mxv = mxs[bm];
            bool pmask = ((v == mxv) && (mxv > 0.f)) || (v > 0.7f);
            if (!(v < 0.3f)) allneg = false;
            if (pmask) {
                pm_sum += 1.f;
                float gcx = (gx1 + gx2) * 0.5f, gcy = (gy1 + gy2) * 0.5f;
                float gw = fmaxf(gx2 - gx1, 1e-6f), gh = fmaxf(gy2 - gy1, 1e-6f);
                float tx = (gcx - acx) / aw;
                float ty = (gcy - acy) / ah;
                float tw = logf(gw / aw);
                float th = logf(gh / ah);
                v_reg += sl1(tx - p0) + sl1(ty - p1) + sl1(tw - p2) + sl1(th - p3);
            }
        }
        v_npos = pm_sum;
        v_pos = pm_sum * softplus_f(-logit);
        if (allneg) { v_nneg = 1.f; v_neg = softplus_f(logit); }

        // fused proposals
        float pcx = acx + p0 * aw;
        float pcy = acy + p1 * ah;
        float pw = aw * expf(p2);
        float ph = ah * expf(p3);
        out[base + (size_t)gid * 4 + 0] = pcx - pw * 0.5f;
        out[base + (size_t)gid * 4 + 1] = pcy - ph * 0.5f;
        out[base + (size_t)gid * 4 + 2] = pcx + pw * 0.5f;
        out[base + (size_t)gid * 4 + 3] = pcy + ph * 0.5f;
    }
    __shared__ float rs[256];
    float vals[5] = {v_npos, v_reg, v_pos, v_neg, v_nneg};
#pragma unroll
    for (int k = 0; k < 5; k++) {
        rs[threadIdx.x] = vals[k];
        __syncthreads();
        for (int s = 128; s; s >>= 1) {
            if (threadIdx.x < s) rs[threadIdx.x] += rs[threadIdx.x + s];
            __syncthreads();
        }
        if (threadIdx.x == 0) g_part[blockIdx.x * 5 + k] = rs[0];
        __syncthreads();
    }
}

// ============ 5) finalize scalar loss ============
__global__ __launch_bounds__(256) void finalize_kernel(float* __restrict__ out) {
    float loc[5] = {0.f, 0.f, 0.f, 0.f, 0.f};
    for (int i = threadIdx.x; i < LOSS_BLOCKS; i += 256) {
#pragma unroll
        for (int k = 0; k < 5; k++) loc[k] += g_part[i * 5 + k];
    }
    __shared__ float sm[256];
    float tot[5];
#pragma unroll
    for (int k = 0; k < 5; k++) {
        sm[threadIdx.x] = loc[k];
        __syncthreads();
        for (int s = 128; s; s >>= 1) {
            if (threadIdx.x < s) sm[threadIdx.x] += sm[threadIdx.x + s];
            __syncthreads();
        }
        tot[k] = sm[0];
        __syncthreads();
    }
    if (threadIdx.x == 0) {
        float n_pos = fmaxf(tot[0], 1.f);
        float n_neg = fmaxf(tot[4], 1.f);
        float reg_loss = tot[1] / (4.f * n_pos);
        float cls_loss = 0.5f * (tot[2] / n_pos + tot[3] / n_neg);
        out[0] = 1.0f * cls_loss + 5.0f * reg_loss;
    }
}

extern "C" void kernel_launch(void* const* d_in, const int* in_sizes, int n_in,
                              void* d_out, int out_size) {
    const float* features = (const float*)d_in[0];
    const float* gt_boxes = (const float*)d_in[1];
    const float* w1       = (const float*)d_in[2];
    const float* b1       = (const float*)d_in[3];
    const float* w_cls    = (const float*)d_in[4];
    const float* b_cls    = (const float*)d_in[5];
    const float* w_box    = (const float*)d_in[6];
    const float* b_box    = (const float*)d_in[7];
    float* out = (float*)d_out;

    int base = out_size - Bn * Nn * 4;
    if (base < 0) base = 0;

    cudaFuncSetAttribute(conv_mma_kernel, cudaFuncAttributeMaxDynamicSharedMemorySize, DYN_SMEM);
    cudaFuncSetAttribute(head_mma_kernel, cudaFuncAttributeMaxDynamicSharedMemorySize, H_SMEM);

    int zitems = Bn * 316 * 64;
    zero_pad_kernel<<<(zitems + 255) / 256, 256>>>();
    prep_a_kernel<<<Bn * Hh * 16, 256>>>(features);
    prep_b_kernel<<<Cc / 2, 256>>>(w1);
    conv_mma_kernel<<<dim3(PTILES, NTILES, Bn), 256, DYN_SMEM>>>(b1);
    misc_kernel<<<(48 * Cc + Nn + 255) / 256, 256>>>(w_cls, w_box);
    head_mma_kernel<<<(Bn * Hh * Ww + 127) / 128, 128, H_SMEM>>>(b_cls, b_box);
    maxiou_kernel<<<Bn * Mm, 256>>>(gt_boxes);
    loss_kernel<<<LOSS_BLOCKS, 256>>>(gt_boxes, out, base);
    finalize_kernel<<<1, 256>>>(out);
}

// round 17
// speedup vs baseline: 1.1594x; 1.0324x over previous
#include <cuda_runtime.h>
#include <cuda_fp16.h>
#include <math.h>
#include <stdint.h>

#define Bn 16
#define Cc 512
#define Hh 50
#define Ww 50
#define Aa 9
#define Nn (Hh*Ww*Aa)   // 22500
#define Mm 16
#define LOSS_BLOCKS ((Bn*Nn + 255)/256)  // 1407

#define PADW 52
#define PROWS 2816
#define Kk 4608
#define PTILES 21
#define NTILES 4

// conv smem: A per-(ci,kh) tile 132 rows x 64ci fp16, 2 stages;
//            B tile 128 co x 64 ci fp16, 3 stages. Row stride 144B.
#define B_MAT 18432                   // 128*144
#define A2_ROWS 132
#define A2_MAT 19072                  // 132*144 = 19008 pad
#define DYN_SMEM (2*A2_MAT + 3*B_MAT) // 93440  -> 2 CTAs/SM

// head GEMM: M=40192, N=48, K=512, fp16 single pass
#define HROWS 40192
#define H_AST 18432                   // 128*144 per stage
#define H_WSTRIDE 1040
#define H_WBYTES (48*H_WSTRIDE)       // 49920
#define H_SMEM (3*H_AST + H_WBYTES)   // 105216
#define H_CHUNKS 8

// -------- scratch --------
__device__ float g_logits[Bn*Nn];
__device__ float g_pred[Bn*Nn*4];
__device__ float g_maxiou[Bn*Mm];
__device__ float g_part[LOSS_BLOCKS*5];
__device__ float4 g_anchor[Nn];
__device__ __align__(16) __half g_af[(size_t)Bn*PROWS*Cc];
__device__ __align__(16) __half g_bf[(size_t)Cc*Kk];
__device__ __align__(16) __half g_xf[(size_t)HROWS*Cc];
__device__ __align__(16) __half g_wf[48*Cc];

// ============ PTX helpers ============
#define CP_ASYNC16(dst, src) \
    asm volatile("cp.async.cg.shared.global [%0], [%1], 16;" :: "r"(dst), "l"(src))
#define CP_COMMIT() asm volatile("cp.async.commit_group;" ::: "memory")
#define CP_WAIT2()  asm volatile("cp.async.wait_group 2;" ::: "memory")
#define CP_WAIT1()  asm volatile("cp.async.wait_group 1;" ::: "memory")
#define CP_WAIT0()  asm volatile("cp.async.wait_group 0;" ::: "memory")

#define LDSM_X4(r0, r1, r2, r3, addr) \
    asm volatile("ldmatrix.sync.aligned.m8n8.x4.shared.b16 {%0,%1,%2,%3}, [%4];" \
        : "=r"(r0), "=r"(r1), "=r"(r2), "=r"(r3) : "r"(addr))
#define LDSM_X2(r0, r1, addr) \
    asm volatile("ldmatrix.sync.aligned.m8n8.x2.shared.b16 {%0,%1}, [%2];" \
        : "=r"(r0), "=r"(r1) : "r"(addr))

#define MMAF16(d, a, b) \
    asm volatile("mma.sync.aligned.m16n8k16.row.col.f32.f16.f16.f32 " \
        "{%0,%1,%2,%3}, {%4,%5,%6,%7}, {%8,%9}, {%0,%1,%2,%3};" \
        : "+f"((d)[0]), "+f"((d)[1]), "+f"((d)[2]), "+f"((d)[3]) \
        : "r"((a)[0]), "r"((a)[1]), "r"((a)[2]), "r"((a)[3]), "r"((b)[0]), "r"((b)[1]))

// ============ shared math helpers ============
__device__ __forceinline__ void anchor_geom(int n, float* ax1, float* ay1, float* ax2, float* ay2) {
    int a  = n % Aa;
    int i1 = (n / Aa) % Hh;
    int i0 = n / (Aa * Hh);
    const float SC[3] = {2.f, 4.f, 6.f};
    const float RA[3] = {0.5f, 1.f, 1.5f};
    float ws = SC[a % 3] * RA[a / 3];
    float hs = SC[a % 3];
    float cx = (float)i0 + 0.5f;
    float cy = (float)i1 + 0.5f;
    *ax1 = fminf(fmaxf(cx - ws * 0.5f, 0.f), 50.f);
    *ax2 = fminf(fmaxf(cx + ws * 0.5f, 0.f), 50.f);
    *ay1 = fminf(fmaxf(cy - hs * 0.5f, 0.f), 50.f);
    *ay2 = fminf(fmaxf(cy + hs * 0.5f, 0.f), 50.f);
}
// noinline: maxiou and loss must produce bitwise-identical iou values,
// and both read anchors from the same g_anchor table.
__device__ __noinline__ float iou_fn(float ax1, float ay1, float ax2, float ay2,
                                     float gx1, float gy1, float gx2, float gy2) {
    float ix1 = fmaxf(ax1, gx1);
    float iy1 = fmaxf(ay1, gy1);
    float ix2 = fminf(ax2, gx2);
    float iy2 = fminf(ay2, gy2);
    float iw = fmaxf(ix2 - ix1, 0.f);
    float ih = fmaxf(iy2 - iy1, 0.f);
    float inter = iw * ih;
    float aa = (ax2 - ax1) * (ay2 - ay1);
    float ag = (gx2 - gx1) * (gy2 - gy1);
    return inter / (aa + ag - inter + 1e-8f);
}
__device__ __forceinline__ float softplus_f(float x) {
    return fmaxf(x, 0.f) + log1pf(expf(-fabsf(x)));
}
__device__ __forceinline__ float sl1(float d) {
    float a = fabsf(d);
    return (a < 1.f) ? 0.5f * d * d : a - 0.5f;
}

// ============ 0) zero the padding positions of the A slab ============
__global__ __launch_bounds__(256) void zero_pad_kernel() {
    int idx = blockIdx.x * 256 + threadIdx.x;
    const int PER = 64;
    int pos_id = idx / PER;
    int which = idx % PER;
    if (pos_id >= Bn * 316) return;
    int b = pos_id / 316;
    int j = pos_id % 316;
    int p;
    if (j < 52) p = j;
    else if (j < 152) { int r = 1 + (j - 52) / 2; p = r * PADW + (((j - 52) & 1) ? 51 : 0); }
    else p = 2652 + (j - 152);
    size_t posbase = (size_t)b * PROWS + p;
    uint4 z = {0, 0, 0, 0};
    ((uint4*)g_af)[posbase * 64 + which] = z;
}

// ============ 0a) features -> padded channel-last fp16 (coalesced) ============
__global__ __launch_bounds__(256) void prep_a_kernel(const float* __restrict__ feat) {
    __shared__ float t[32][53];
    int blk = blockIdx.x;
    int ci0 = (blk % 16) * 32;
    int h   = (blk / 16) % Hh;
    int b   = blk / (16 * Hh);
    int tx = threadIdx.x & 31, ty = threadIdx.x >> 5;
#pragma unroll
    for (int r = 0; r < 4; r++) {
        int ci = ci0 + ty + r * 8;
        const float* row = feat + ((size_t)(b * Cc + ci) * Hh + h) * Ww;
        t[ty + r * 8][tx] = row[tx];
        if (tx < 18) t[ty + r * 8][tx + 32] = row[tx + 32];
    }
    __syncthreads();
    size_t base = ((size_t)b * PROWS + (h + 1) * PADW + 1) * Cc + ci0;
#pragma unroll
    for (int r = 0; r < 7; r++) {
        int w = ty + r * 8;
        if (w < Ww)
            g_af[base + (size_t)w * Cc + tx] = __float2half(t[tx][w]);
    }
}

// ============ 0b) conv weights -> K-major fp16 (coalesced via smem) ============
__global__ __launch_bounds__(256) void prep_b_kernel(const float* __restrict__ w1) {
    __shared__ float t[2 * Kk];
    int co0 = blockIdx.x * 2;
    int tid = threadIdx.x;
    const float* src = w1 + (size_t)co0 * Kk;
#pragma unroll
    for (int i = 0; i < 36; i++)
        t[tid + i * 256] = src[tid + i * 256];
    __syncthreads();
#pragma unroll
    for (int i = 0; i < 36; i++) {
        int idx = tid + i * 256;
        int c = idx / Kk;
        int r = idx - c * Kk;             // pos*512 + ci
        int pos = r >> 9;
        int ci  = r & 511;
        g_bf[(size_t)(co0 + c) * Kk + r] = __float2half(t[c * Kk + ci * 9 + pos]);
    }
}

// ============ 0c) head weights + anchors + g_maxiou init ============
__global__ __launch_bounds__(256) void misc_kernel(
    const float* __restrict__ w_cls, const float* __restrict__ w_box) {
    int idx = blockIdx.x * 256 + threadIdx.x;
    if (idx < Bn * Mm) g_maxiou[idx] = 0.f;   // init for maxiou atomicMax
    if (idx < 48 * Cc) {
        int c = idx % Cc;
        int o = idx / Cc;
        float v = 0.f;
        if (o < 9) v = w_cls[o * Cc + c];
        else if (o < 45) v = w_box[(o - 9) * Cc + c];
        g_wf[idx] = __float2half(v);
    } else {
        int n = idx - 48 * Cc;
        if (n < Nn) {
            float a0, a1, a2, a3;
            anchor_geom(n, &a0, &a1, &a2, &a3);
            g_anchor[n] = make_float4(a0, a1, a2, a3);
        }
    }
}

// ============ 1) conv implicit GEMM fp16 single-pass (256 thr, 2x4 warps) ============
__device__ __forceinline__ void conv_load_A2(
    uint32_t smb, int abuf, int grp, int p0, const __half* Af, int tid) {
    uint32_t st = smb + abuf * A2_MAT;
    int ci0 = (grp / 3) * 64;
    int rbase = p0 + (grp % 3) * PADW;
#pragma unroll
    for (int i = 0; i < 5; i++) {
        int idx = tid + i * 256;
        if (idx < A2_ROWS * 8) {
            int m = idx >> 3, g = idx & 7;
            CP_ASYNC16(st + m * 144 + g * 16, Af + ((size_t)(rbase + m) * Cc + ci0 + g * 8));
        }
    }
    CP_COMMIT();
}
__device__ __forceinline__ void conv_load_B2(
    uint32_t smb, int bbuf, int t, int co0, int tid) {
    uint32_t st = smb + 2 * A2_MAT + bbuf * B_MAT;
    int k0 = (t % 9) * 512 + (t / 9) * 64;
#pragma unroll
    for (int i = 0; i < 4; i++) {
        int idx = tid + i * 256;
        int m = idx >> 3, g = idx & 7;
        CP_ASYNC16(st + m * 144 + g * 16, g_bf + ((size_t)(co0 + m) * Kk + k0 + g * 8));
    }
    CP_COMMIT();
}

__global__ __launch_bounds__(256, 2) void conv_mma_kernel(const float* __restrict__ b1) {
    extern __shared__ __align__(128) char smc[];
    uint32_t smb = (uint32_t)__cvta_generic_to_shared(smc);
    int tid = threadIdx.x;
    int wid = tid >> 5;
    int lane = tid & 31;
    int p0  = blockIdx.x * 128;
    int co0 = blockIdx.y * 128;
    int b   = blockIdx.z;
    int warp_m = wid >> 2;
    int warp_n = wid & 3;

    const __half* Af = g_af + (size_t)b * PROWS * Cc;

    float acc[4][4][4];
#pragma unroll
    for (int i = 0; i < 4; i++)
#pragma unroll
        for (int j = 0; j < 4; j++)
#pragma unroll
            for (int k = 0; k < 4; k++) acc[i][j][k] = 0.f;

    conv_load_A2(smb, 0, 0, p0, Af, tid);
    conv_load_B2(smb, 0, 0, co0, tid);
    conv_load_B2(smb, 1, 1, co0, tid);

    int a_row = warp_m * 64 + (lane & 15);
    int a_col = (lane >> 4) << 3;
    int b_rowX4 = warp_n * 32 + (lane & 7) + ((lane >> 4) << 3);
    int b_colX4 = ((lane >> 3) & 1) << 3;

    for (int t = 0; t < 72; t++) {
        int grp = t / 3;
        int kw  = t % 3;
        if (t == 71) CP_WAIT0();
        else if (kw == 2 && grp < 23) CP_WAIT2();
        else CP_WAIT1();
        __syncthreads();

        uint32_t sA = smb + (grp & 1) * A2_MAT + (uint32_t)kw * 144;
        uint32_t sB = smb + 2 * A2_MAT + (t % 3) * B_MAT;

#pragma unroll
        for (int ks = 0; ks < 4; ks++) {
            uint32_t ah[4][4], bh[4][2];
#pragma unroll
            for (int mf = 0; mf < 4; mf++) {
                uint32_t off = (uint32_t)(a_row + mf * 16) * 144 + (a_col + ks * 16) * 2;
                LDSM_X4(ah[mf][0], ah[mf][1], ah[mf][2], ah[mf][3], sA + off);
            }
#pragma unroll
            for (int np = 0; np < 2; np++) {
                uint32_t off = (uint32_t)(b_rowX4 + np * 16) * 144 +
                               (b_colX4 + ks * 16) * 2;
                LDSM_X4(bh[2 * np][0], bh[2 * np][1],
                        bh[2 * np + 1][0], bh[2 * np + 1][1], sB + off);
            }
#pragma unroll
            for (int mf = 0; mf < 4; mf++)
#pragma unroll
                for (int nf = 0; nf < 4; nf++)
                    MMAF16(acc[mf][nf], ah[mf], bh[nf]);
        }
        if (kw == 1 && grp < 23)
            conv_load_A2(smb, (grp + 1) & 1, grp + 1, p0, Af, tid);
        if (t + 2 < 72) {
            int tn = t + 2;
            int gn = tn / 3, kn = tn % 3;
            int tt = (gn / 3) * 9 + (gn % 3) * 3 + kn;
            conv_load_B2(smb, tn % 3, tt, co0, tid);
        }
    }

#pragma unroll
    for (int nf = 0; nf < 4; nf++) {
        int colg = co0 + warp_n * 32 + nf * 8 + (lane & 3) * 2;
        float bv0 = __ldg(&b1[colg]);
        float bv1 = __ldg(&b1[colg + 1]);
#pragma unroll
        for (int mf = 0; mf < 4; mf++) {
            int row0 = p0 + warp_m * 64 + mf * 16 + (lane >> 2);
#pragma unroll
            for (int half = 0; half < 2; half++) {
                int p = row0 + half * 8;
                int h = p / PADW, w = p % PADW;
                if (h < Hh && w < Ww) {
                    __half2 v;
                    v.x = __float2half(acc[mf][nf][half * 2 + 0] + bv0);
                    v.y = __float2half(acc[mf][nf][half * 2 + 1] + bv1);
                    size_t off = ((size_t)((b * Hh + h) * Ww + w)) * Cc + colg;
                    *(__half2*)&g_xf[off] = v;
                }
            }
        }
    }
}

// ============ 2) heads as fp16 MMA GEMM ============
__device__ __forceinline__ void head_load_chunk(uint32_t smb, int stage, int kc,
                                                int p0, int tid) {
    uint32_t st = smb + stage * H_AST;
#pragma unroll
    for (int i = 0; i < 8; i++) {
        int idx = tid + i * 128;
        int r = idx >> 3;
        int g = idx & 7;
        const __half* src = g_xf + ((size_t)(p0 + r) * Cc + kc * 64 + g * 8);
        CP_ASYNC16(st + r * 144 + g * 16, src);
    }
}

__global__ __launch_bounds__(128, 1) void head_mma_kernel(
    const float* __restrict__ b_cls, const float* __restrict__ b_box) {
    extern __shared__ __align__(128) char smc[];
    uint32_t smb = (uint32_t)__cvta_generic_to_shared(smc);
    uint32_t smW = smb + 3 * H_AST;
    int tid = threadIdx.x;
    int wid = tid >> 5;
    int lane = tid & 31;
    int p0 = blockIdx.x * 128;

    {
#pragma unroll
        for (int i = 0; i < 24; i++) {
            int linear = tid + i * 128;
            int row = linear / 64;
            int gc = linear % 64;
            const __half* src = g_wf + (size_t)row * Cc + gc * 8;
            CP_ASYNC16(smW + row * H_WSTRIDE + gc * 16, src);
        }
        head_load_chunk(smb, 0, 0, p0, tid);
        CP_COMMIT();
    }
    head_load_chunk(smb, 1, 1, p0, tid);
    CP_COMMIT();

    float acc[2][6][4];
#pragma unroll
    for (int i = 0; i < 2; i++)
#pragma unroll
        for (int j = 0; j < 6; j++)
#pragma unroll
            for (int k = 0; k < 4; k++) acc[i][j][k] = 0.f;

    int a_row = wid * 32 + (lane & 15);
    int a_col = (lane >> 4) << 3;
    int b_row = lane & 7;
    int b_col = ((lane >> 3) & 1) << 3;

    for (int kc = 0; kc < H_CHUNKS; kc++) {
        int s = kc % 3;
        if (kc + 2 < H_CHUNKS) {
            CP_WAIT1();
            __syncthreads();
            head_load_chunk(smb, (kc + 2) % 3, kc + 2, p0, tid);
            CP_COMMIT();
        } else if (kc + 1 < H_CHUNKS) {
            CP_WAIT1();
            __syncthreads();
        } else {
            CP_WAIT0();
            __syncthreads();
        }
        uint32_t sA = smb + s * H_AST;
#pragma unroll
        for (int ks = 0; ks < 4; ks++) {
            uint32_t ah[2][4], bh[6][2];
#pragma unroll
            for (int mf = 0; mf < 2; mf++) {
                uint32_t off = (uint32_t)(a_row + mf * 16) * 144 + (a_col + ks * 16) * 2;
                LDSM_X4(ah[mf][0], ah[mf][1], ah[mf][2], ah[mf][3], sA + off);
            }
#pragma unroll
            for (int nf = 0; nf < 6; nf++) {
                uint32_t off = (uint32_t)(b_row + nf * 8) * H_WSTRIDE +
                               (kc * 64 + b_col + ks * 16) * 2;
                LDSM_X2(bh[nf][0], bh[nf][1], smW + off);
            }
#pragma unroll
            for (int mf = 0; mf < 2; mf++)
#pragma unroll
                for (int nf = 0; nf < 6; nf++)
                    MMAF16(acc[mf][nf], ah[mf], bh[nf]);
        }
    }

#pragma unroll
    for (int nf = 0; nf < 6; nf++) {
        int o0 = nf * 8 + (lane & 3) * 2;
#pragma unroll
        for (int mf = 0; mf < 2; mf++) {
            int row0 = p0 + wid * 32 + mf * 16 + (lane >> 2);
#pragma unroll
            for (int half = 0; half < 2; half++) {
                int pix = row0 + half * 8;
                if (pix < Bn * Hh * Ww) {
                    int b = pix / (Hh * Ww);
                    int hw = pix % (Hh * Ww);
#pragma unroll
                    for (int q = 0; q < 2; q++) {
                        int o = o0 + q;
                        if (o < 45) {
                            float v = acc[mf][nf][half * 2 + q];
                            if (o < 9) {
                                v += __ldg(&b_cls[o]);
                                g_logits[b * Nn + hw * Aa + o] = v;
                            } else {
                                int d = o - 9;
                                v += __ldg(&b_box[d]);
                                g_pred[((size_t)(b * Nn + hw * Aa + d / 4)) * 4 + (d & 3)] = v;
                            }
                        }
                    }
                }
            }
        }
    }
}

// ============ 3) max IoU per (b, gt), split 4-way + exact atomicMax ============
// iou >= 0 always, so integer atomicMax on float bits == exact float max;
// result is bitwise identical to the sequential reduction.
__global__ __launch_bounds__(256) void maxiou_kernel(const float* __restrict__ gt_boxes) {
    int blk = blockIdx.x;
    int bm = blk >> 2;
    int s  = blk & 3;
    float gx1 = gt_boxes[bm * 4 + 0] * 0.0625f;
    float gy1 = gt_boxes[bm * 4 + 1] * 0.0625f;
    float gx2 = gt_boxes[bm * 4 + 2] * 0.0625f;
    float gy2 = gt_boxes[bm * 4 + 3] * 0.0625f;
    int n0 = s * (Nn / 4);
    int n1 = n0 + (Nn / 4);
    float mx = 0.f;
    for (int n = n0 + threadIdx.x; n < n1; n += 256) {
        float4 a = g_anchor[n];
        float v = iou_fn(a.x, a.y, a.z, a.w, gx1, gy1, gx2, gy2);
        mx = fmaxf(mx, v);
    }
    __shared__ float sm[256];
    sm[threadIdx.x] = mx;
    __syncthreads();
    for (int st = 128; st; st >>= 1) {
        if (threadIdx.x < st) sm[threadIdx.x] = fmaxf(sm[threadIdx.x], sm[threadIdx.x + st]);
        __syncthreads();
    }
    if (threadIdx.x == 0)
        atomicMax((int*)&g_maxiou[bm], __float_as_int(sm[0]));
}

// ============ 4) per-anchor losses + proposals (fused) ============
__global__ __launch_bounds__(256) void loss_kernel(const float* __restrict__ gt_boxes,
                                                   float* __restrict__ out, int base) {
    __shared__ float gts[Bn * Mm * 4];
    __shared__ float mxs[Bn * Mm];
    for (int i = threadIdx.x; i < Bn * Mm * 4; i += 256) gts[i] = gt_boxes[i] * 0.0625f;
    for (int i = threadIdx.x; i < Bn * Mm; i += 256) mxs[i] = g_maxiou[i];
    __syncthreads();

    int gid = blockIdx.x * 256 + threadIdx.x;
    float v_npos = 0.f, v_reg = 0.f, v_pos = 0.f, v_neg = 0.f, v_nneg = 0.f;
    if (gid < Bn * Nn) {
        int b = gid / Nn;
        int n = gid % Nn;
        float4 anc = g_anchor[n];
        float ax1 = anc.x, ay1 = anc.y, ax2 = anc.z, ay2 = anc.w;
        float acx = (ax1 + ax2) * 0.5f, acy = (ay1 + ay2) * 0.5f;
        float aw = fmaxf(ax2 - ax1, 1e-6f), ah = fmaxf(ay2 - ay1, 1e-6f);
        float p0 = g_pred[(size_t)gid * 4 + 0];
        float p1 = g_pred[(size_t)gid * 4 + 1];
        float p2 = g_pred[(size_t)gid * 4 + 2];
        float p3 = g_pred[(size_t)gid * 4 + 3];
        float logit = g_logits[gid];
        bool allneg = true;
        float pm_sum = 0.f;
        for (int m = 0; m < Mm; m++) {
            int bm = b * Mm + m;
            float gx1 = gts[bm * 4 + 0];
            float gy1 = gts[bm * 4 + 1];
            float gx2 = gts[bm * 4 + 2];
            float gy2 = gts[bm * 4 + 3];
            float v = iou_fn(ax1, ay1, ax2, ay2, gx1, gy1, gx2, gy2);
            float mxv = mxs[bm];
            bool pmask = ((v == mxv) && (mxv > 0.f)) || (v > 0.7f);
            if (!(v < 0.3f)) allneg = false;
            if (pmask) {
                pm_sum += 1.f;
                float gcx = (gx1 + gx2) * 0.5f, gcy = (gy1 + gy2) * 0.5f;
                float gw = fmaxf(gx2 - gx1, 1e-6f), gh = fmaxf(gy2 - gy1, 1e-6f);
                float tx = (gcx - acx) / aw;
                float ty = (gcy - acy) / ah;
                float tw = logf(gw / aw);
                float th = logf(gh / ah);
                v_reg += sl1(tx - p0) + sl1(ty - p1) + sl1(tw - p2) + sl1(th - p3);
            }
        }
        v_npos = pm_sum;
        v_pos = pm_sum * softplus_f(-logit);
        if (allneg) { v_nneg = 1.f; v_neg = softplus_f(logit); }

        float pcx = acx + p0 * aw;
        float pcy = acy + p1 * ah;
        float pw = aw * expf(p2);
        float ph = ah * expf(p3);
        out[base + (size_t)gid * 4 + 0] = pcx - pw * 0.5f;
        out[base + (size_t)gid * 4 + 1] = pcy - ph * 0.5f;
        out[base + (size_t)gid * 4 + 2] = pcx + pw * 0.5f;
        out[base + (size_t)gid * 4 + 3] = pcy + ph * 0.5f;
    }
    __shared__ float rs[256];
    float vals[5] = {v_npos, v_reg, v_pos, v_neg, v_nneg};
#pragma unroll
    for (int k = 0; k < 5; k++) {
        rs[threadIdx.x] = vals[k];
        __syncthreads();
        for (int s = 128; s; s >>= 1) {
            if (threadIdx.x < s) rs[threadIdx.x] += rs[threadIdx.x + s];
            __syncthreads();
        }
        if (threadIdx.x == 0) g_part[blockIdx.x * 5 + k] = rs[0];
        __syncthreads();
    }
}

// ============ 5) finalize scalar loss ============
__global__ __launch_bounds__(256) void finalize_kernel(float* __restrict__ out) {
    float loc[5] = {0.f, 0.f, 0.f, 0.f, 0.f};
    for (int i = threadIdx.x; i < LOSS_BLOCKS; i += 256) {
#pragma unroll
        for (int k = 0; k < 5; k++) loc[k] += g_part[i * 5 + k];
    }
    __shared__ float sm[256];
    float tot[5];
#pragma unroll
    for (int k = 0; k < 5; k++) {
        sm[threadIdx.x] = loc[k];
        __syncthreads();
        for (int s = 128; s; s >>= 1) {
            if (threadIdx.x < s) sm[threadIdx.x] += sm[threadIdx.x + s];
            __syncthreads();
        }
        tot[k] = sm[0];
        __syncthreads();
    }
    if (threadIdx.x == 0) {
        float n_pos = fmaxf(tot[0], 1.f);
        float n_neg = fmaxf(tot[4], 1.f);
        float reg_loss = tot[1] / (4.f * n_pos);
        float cls_loss = 0.5f * (tot[2] / n_pos + tot[3] / n_neg);
        out[0] = 1.0f * cls_loss + 5.0f * reg_loss;
    }
}

extern "C" void kernel_launch(void* const* d_in, const int* in_sizes, int n_in,
                              void* d_out, int out_size) {
    const float* features = (const float*)d_in[0];
    const float* gt_boxes = (const float*)d_in[1];
    const float* w1       = (const float*)d_in[2];
    const float* b1       = (const float*)d_in[3];
    const float* w_cls    = (const float*)d_in[4];
    const float* b_cls    = (const float*)d_in[5];
    const float* w_box    = (const float*)d_in[6];
    const float* b_box    = (const float*)d_in[7];
    float* out = (float*)d_out;

    int base = out_size - Bn * Nn * 4;
    if (base < 0) base = 0;

    cudaFuncSetAttribute(conv_mma_kernel, cudaFuncAttributeMaxDynamicSharedMemorySize, DYN_SMEM);
    cudaFuncSetAttribute(head_mma_kernel, cudaFuncAttributeMaxDynamicSharedMemorySize, H_SMEM);

    int zitems = Bn * 316 * 64;
    zero_pad_kernel<<<(zitems + 255) / 256, 256>>>();
    prep_a_kernel<<<Bn * Hh * 16, 256>>>(features);
    prep_b_kernel<<<Cc / 2, 256>>>(w1);
    conv_mma_kernel<<<dim3(PTILES, NTILES, Bn), 256, DYN_SMEM>>>(b1);
    misc_kernel<<<(48 * Cc + Nn + 255) / 256, 256>>>(w_cls, w_box);
    head_mma_kernel<<<(Bn * Hh * Ww + 127) / 128, 128, H_SMEM>>>(b_cls, b_box);
    maxiou_kernel<<<Bn * Mm * 4, 256>>>(gt_boxes);
    loss_kernel<<<LOSS_BLOCKS, 256>>>(gt_boxes, out, base);
    finalize_kernel<<<1, 256>>>(out);
}